// round 1
// baseline (speedup 1.0000x reference)
#include <cuda_runtime.h>
#include <cuda_bf16.h>
#include <cstdint>

#define GRIDSZ 32
#define NPX 1024
#define NE 1984
#define KTOP 256
#define NIMG 24
#define SINK_ITERS 150

// ---------------- global scratch (no allocations allowed) ----------------
__device__ float g_v[NIMG][NPX];             // 24 pooled 32x32 images
__device__ float g_bd[NIMG][2][2][KTOP];     // [img][dim][b/d][k]
__device__ float g_w[NIMG];                  // per-problem Wasserstein values

// ---------------- helpers ----------------
__device__ __forceinline__ unsigned ordf(float f) {
    unsigned u = __float_as_uint(f);
    return (u & 0x80000000u) ? ~u : (u | 0x80000000u);  // monotone float->uint
}

// block = 256 threads (8 warps) assumed
__device__ __forceinline__ float blkMax(float v, float* r8) {
    #pragma unroll
    for (int o = 16; o; o >>= 1) v = fmaxf(v, __shfl_xor_sync(0xffffffffu, v, o));
    if ((threadIdx.x & 31) == 0) r8[threadIdx.x >> 5] = v;
    __syncthreads();
    float m = r8[0];
    #pragma unroll
    for (int k = 1; k < 8; ++k) m = fmaxf(m, r8[k]);
    __syncthreads();
    return m;
}

__device__ __forceinline__ float blkSum(float v, float* r8) {
    #pragma unroll
    for (int o = 16; o; o >>= 1) v += __shfl_xor_sync(0xffffffffu, v, o);
    if ((threadIdx.x & 31) == 0) r8[threadIdx.x >> 5] = v;
    __syncthreads();
    float s = r8[0];
    #pragma unroll
    for (int k = 1; k < 8; ++k) s += r8[k];
    __syncthreads();
    return s;
}

__device__ __forceinline__ void edge_uv(int e, int& u, int& v) {
    if (e < 992) {            // horizontal edges: _idx[:, :-1] -> _idx[:, 1:]
        int rr = e / 31, cc = e - rr * 31;
        u = rr * 32 + cc; v = u + 1;
    } else {                  // vertical edges: _idx[:-1, :] -> _idx[1:, :]
        u = e - 992; v = u + 32;
    }
}

__device__ void bitonic2048(unsigned long long* keys) {
    int tid = threadIdx.x;
    for (unsigned k = 2; k <= 2048; k <<= 1)
        for (unsigned j = k >> 1; j > 0; j >>= 1) {
            __syncthreads();
            for (unsigned i = tid; i < 2048; i += 256) {
                unsigned l = i ^ j;
                if (l > i) {
                    unsigned long long a = keys[i], b = keys[l];
                    bool up = ((i & k) == 0);
                    if ((a > b) == up) { keys[i] = b; keys[l] = a; }
                }
            }
        }
    __syncthreads();
}

// ---------------- stage 1: softmax + one-hot + adaptive pool ----------------
__global__ void pool_kernel(const float* __restrict__ x, const int* __restrict__ y) {
    int idx = blockIdx.x * blockDim.x + threadIdx.x;
    if (idx >= NIMG * NPX) return;
    int m = idx >> 10;
    int cell = idx & 1023;
    int gi = cell >> 5, gj = cell & 31;
    float acc = 0.f;
    if (m < 12) {
        int b = m / 3, c = m % 3 + 1;
        const float* xb = x + (size_t)b * 4 * 65536;
        for (int pi = 0; pi < 8; ++pi) {
            int off0 = (gi * 8 + pi) * 256 + gj * 8;
            #pragma unroll
            for (int pj = 0; pj < 8; ++pj) {
                int off = off0 + pj;
                float x0 = xb[off], x1 = xb[65536 + off],
                      x2 = xb[131072 + off], x3 = xb[196608 + off];
                float mx = fmaxf(fmaxf(x0, x1), fmaxf(x2, x3));
                float e0 = __expf(x0 - mx), e1 = __expf(x1 - mx),
                      e2 = __expf(x2 - mx), e3 = __expf(x3 - mx);
                float ec = (c == 1) ? e1 : ((c == 2) ? e2 : e3);
                acc += ec / (e0 + e1 + e2 + e3);
            }
        }
    } else {
        int mm = m - 12, b = mm / 3, c = mm % 3 + 1;
        const int* yb = y + (size_t)b * 65536;
        int cnt = 0;
        for (int pi = 0; pi < 8; ++pi) {
            int off0 = (gi * 8 + pi) * 256 + gj * 8;
            #pragma unroll
            for (int pj = 0; pj < 8; ++pj) cnt += (yb[off0 + pj] == c);
        }
        acc = (float)cnt;
    }
    g_v[m][cell] = acc * 0.015625f;   // /64
}

// ---------------- stage 2: persistence diagrams ----------------
// block b: image m = b>>1, run r = b&1 (0 = sublevel incl. essential, 1 = superlevel)
__global__ void diagram_kernel() {
    int m = blockIdx.x >> 1;
    int r = blockIdx.x & 1;
    __shared__ float v[NPX];
    __shared__ unsigned long long keys[2048];
    __shared__ float bArr[2048], dArr[2048];
    __shared__ int parent[NPX];
    __shared__ float birth[NPX];
    __shared__ float r8[8];
    int tid = threadIdx.x;

    for (int i = tid; i < NPX; i += 256) {
        float val = g_v[m][i];
        if (r) val = -val;
        v[i] = val; birth[i] = val; parent[i] = i;
    }
    __syncthreads();

    // edge sort keys: stable ascending by weight, tie-break original edge index
    for (int e = tid; e < 2048; e += 256) {
        unsigned long long key = ~0ULL;
        if (e < NE) {
            int u, w2; edge_uv(e, u, w2);
            float w = fmaxf(v[u], v[w2]);
            key = ((unsigned long long)ordf(w) << 32) | (unsigned)e;
        }
        keys[e] = key;
    }
    float mn = v[tid], mx = v[tid];
    for (int i = tid + 256; i < NPX; i += 256) { mn = fminf(mn, v[i]); mx = fmaxf(mx, v[i]); }

    bitonic2048(keys);
    float vmax = blkMax(mx, r8);
    float vmin = -blkMax(-mn, r8);

    // serial Kruskal union-find with elder rule (thread 0)
    if (tid == 0) {
        for (int s = 0; s < NE; ++s) {
            int e = (int)(unsigned)keys[s];
            int u, w2; edge_uv(e, u, w2);
            float w = fmaxf(v[u], v[w2]);
            int ru = u;
            for (;;) { int pu = parent[ru]; if (pu == ru) break;
                       int gu = parent[pu]; parent[ru] = gu; ru = gu; }
            int rv = w2;
            for (;;) { int pv = parent[rv]; if (pv == rv) break;
                       int gv = parent[pv]; parent[rv] = gv; rv = gv; }
            float b, d;
            if (ru == rv) { b = w; d = w; }
            else {
                float bu = birth[ru], bv = birth[rv];
                b = fmaxf(bu, bv); d = w;
                if (bu <= bv) { parent[rv] = ru; birth[ru] = fminf(bu, bv); }
                else          { parent[ru] = rv; birth[rv] = fminf(bu, bv); }
            }
            bArr[s] = b; dArr[s] = d;
        }
        if (r == 0) { bArr[NE] = vmin; dArr[NE] = vmax; }  // essential H0 class
    }
    __syncthreads();

    // top-K by persistence, ties -> lowest index (replicates jax.lax.top_k)
    int limit = (r == 0) ? NE + 1 : NE;
    for (int e = tid; e < 2048; e += 256) {
        unsigned long long key = ~0ULL;
        if (e < limit) {
            float pval = dArr[e] - bArr[e];
            key = ((unsigned long long)(~ordf(pval)) << 32) | (unsigned)e;
        }
        keys[e] = key;
    }
    bitonic2048(keys);

    if (tid < KTOP) {
        int s = (int)(unsigned)keys[tid];
        if (r == 0) {
            g_bd[m][0][0][tid] = bArr[s];
            g_bd[m][0][1][tid] = dArr[s];
        } else {                      // b1 = -nd, d1 = -nb
            g_bd[m][1][0][tid] = -dArr[s];
            g_bd[m][1][1][tid] = -bArr[s];
        }
    }
}

// ---------------- stage 3: entropic Sinkhorn ----------------
// Rows/cols >= K of C are identical -> collapse to a single scalar potential
// (f2, g2), which cuts exp work 4x vs the naive 512x512 sweep.
__global__ void sinkhorn_kernel() {
    int p = blockIdx.x;
    int dim = (p < 12) ? 0 : 1;
    int img = (p < 12) ? p : p - 12;
    __shared__ float2 Ap[KTOP], Bp[KTOP];
    __shared__ float fS[KTOP], gS[KTOP];
    __shared__ float r8[8];
    __shared__ float shv[2];   // [0]=f2 (diag rows), [1]=g2 (diag cols)
    int t = threadIdx.x;

    float ab = g_bd[img][dim][0][t];
    float ad = g_bd[img][dim][1][t];
    float bb = g_bd[12 + img][dim][0][t];
    float bd = g_bd[12 + img][dim][1][t];
    Ap[t] = make_float2(ab, ad);
    Bp[t] = make_float2(bb, bd);
    float dai = 0.5f * (ad - ab);
    float dbj = 0.5f * (bd - bb);
    fS[t] = 0.f; gS[t] = 0.f;
    if (t < 2) shv[t] = 0.f;
    __syncthreads();

    // eps = 0.02 * max(max(C), 1e-6)
    float mC = fmaxf(dai, dbj);
    for (int j = 0; j < KTOP; ++j) {
        float2 q = Bp[j];
        mC = fmaxf(mC, fmaxf(fabsf(ab - q.x), fabsf(ad - q.y)));
    }
    float maxC = blkMax(mC, r8);
    float eps = 0.02f * fmaxf(maxC, 1e-6f);
    float ie = 1.f / eps;

    for (int it = 0; it < SINK_ITERS; ++it) {
        // ---- f update (from g) ----
        float g2 = shv[1];
        float tvt = (g2 - dai) * ie;       // 256 identical tail elems of row t
        float mrow = tvt;
        #pragma unroll 4
        for (int j = 0; j < KTOP; ++j) {
            float2 q = Bp[j];
            float c = fmaxf(fabsf(ab - q.x), fabsf(ad - q.y));
            mrow = fmaxf(mrow, (gS[j] - c) * ie);
        }
        float s = 256.f * __expf(tvt - mrow);
        #pragma unroll 4
        for (int j = 0; j < KTOP; ++j) {
            float2 q = Bp[j];
            float c = fmaxf(fabsf(ab - q.x), fabsf(ad - q.y));
            s += __expf((gS[j] - c) * ie - mrow);
        }
        float fnew = -eps * (mrow + __logf(s));
        // shared diagonal-row potential f2
        float et = (gS[t] - dbj) * ie;
        float tg = g2 * ie;
        float M2 = blkMax(fmaxf(et, tg), r8);
        float S2 = blkSum(__expf(et - M2), r8) + 256.f * __expf(tg - M2);
        float f2new = -eps * (M2 + __logf(S2));
        __syncthreads();
        fS[t] = fnew;
        if (t == 0) shv[0] = f2new;
        __syncthreads();

        // ---- g update (from new f) ----
        float f2 = shv[0];
        float tvb = (f2 - dbj) * ie;
        float mcol = tvb;
        #pragma unroll 4
        for (int i = 0; i < KTOP; ++i) {
            float2 q = Ap[i];
            float c = fmaxf(fabsf(q.x - bb), fabsf(q.y - bd));
            mcol = fmaxf(mcol, (fS[i] - c) * ie);
        }
        s = 256.f * __expf(tvb - mcol);
        #pragma unroll 4
        for (int i = 0; i < KTOP; ++i) {
            float2 q = Ap[i];
            float c = fmaxf(fabsf(q.x - bb), fabsf(q.y - bd));
            s += __expf((fS[i] - c) * ie - mcol);
        }
        float gnew = -eps * (mcol + __logf(s));
        float eg = (fS[t] - dai) * ie;
        float tf = f2 * ie;
        float M3 = blkMax(fmaxf(eg, tf), r8);
        float S3 = blkSum(__expf(eg - M3), r8) + 256.f * __expf(tf - M3);
        float g2new = -eps * (M3 + __logf(S3));
        __syncthreads();
        gS[t] = gnew;
        if (t == 0) shv[1] = g2new;
        __syncthreads();
    }

    // ---- final cost sum(P*C); zero-cost block contributes nothing ----
    float fi = fS[t];
    float g2 = shv[1], f2 = shv[0];
    float tot = 256.f * __expf((fi + g2 - dai) * ie) * dai
              + 256.f * __expf((f2 + gS[t] - dbj) * ie) * dbj;
    for (int j = 0; j < KTOP; ++j) {
        float2 q = Bp[j];
        float c = fmaxf(fabsf(ab - q.x), fabsf(ad - q.y));
        tot += __expf((fi + gS[j] - c) * ie) * c;
    }
    tot = blkSum(tot, r8);
    if (t == 0) g_w[p] = tot;
}

// ---------------- stage 4: fixed-order deterministic reduction ----------------
__global__ void final_kernel(float* out) {
    float s0 = 0.f, s1 = 0.f;
    for (int i = 0; i < 12; ++i) s0 += g_w[i];
    for (int i = 12; i < 24; ++i) s1 += g_w[i];
    out[0] = (s0 + s1) * 0.25f;   // / B
}

extern "C" void kernel_launch(void* const* d_in, const int* in_sizes, int n_in,
                              void* d_out, int out_size) {
    (void)in_sizes; (void)n_in; (void)out_size;
    const float* x = (const float*)d_in[0];
    const int* y = (const int*)d_in[1];
    pool_kernel<<<(NIMG * NPX + 255) / 256, 256>>>(x, y);
    diagram_kernel<<<48, 256>>>();
    sinkhorn_kernel<<<24, 256>>>();
    final_kernel<<<1, 1>>>((float*)d_out);
}

// round 3
// speedup vs baseline: 2.7361x; 2.7361x over previous
#include <cuda_runtime.h>
#include <cuda_bf16.h>
#include <cstdint>

#define GRIDSZ 32
#define NPX 1024
#define NE 1984
#define KTOP 256
#define NIMG 24
#define SINK_ITERS 150
#define CLU 4            // cluster size for sinkhorn

// ---------------- global scratch ----------------
__device__ float g_v[NIMG][NPX];
__device__ float g_bd[NIMG][2][2][KTOP];
__device__ float g_wpart[NIMG * CLU];

// ---------------- helpers ----------------
__device__ __forceinline__ unsigned ordf(float f) {
    unsigned u = __float_as_uint(f);
    return (u & 0x80000000u) ? ~u : (u | 0x80000000u);
}

__device__ __forceinline__ float blkMax(float v, float* r8) {
    #pragma unroll
    for (int o = 16; o; o >>= 1) v = fmaxf(v, __shfl_xor_sync(0xffffffffu, v, o));
    if ((threadIdx.x & 31) == 0) r8[threadIdx.x >> 5] = v;
    __syncthreads();
    float m = r8[0];
    #pragma unroll
    for (int k = 1; k < 8; ++k) m = fmaxf(m, r8[k]);
    __syncthreads();
    return m;
}
__device__ __forceinline__ float blkSum(float v, float* r8) {
    #pragma unroll
    for (int o = 16; o; o >>= 1) v += __shfl_xor_sync(0xffffffffu, v, o);
    if ((threadIdx.x & 31) == 0) r8[threadIdx.x >> 5] = v;
    __syncthreads();
    float s = r8[0];
    #pragma unroll
    for (int k = 1; k < 8; ++k) s += r8[k];
    __syncthreads();
    return s;
}

__device__ __forceinline__ void edge_uv(int e, int& u, int& v) {
    if (e < 992) { int rr = e / 31, cc = e - rr * 31; u = rr * 32 + cc; v = u + 1; }
    else { u = e - 992; v = u + 32; }
}

__device__ void bitonic2048(unsigned long long* keys) {
    int tid = threadIdx.x;
    for (unsigned k = 2; k <= 2048; k <<= 1)
        for (unsigned j = k >> 1; j > 0; j >>= 1) {
            __syncthreads();
            for (unsigned i = tid; i < 2048; i += 256) {
                unsigned l = i ^ j;
                if (l > i) {
                    unsigned long long a = keys[i], b = keys[l];
                    bool up = ((i & k) == 0);
                    if ((a > b) == up) { keys[i] = b; keys[l] = a; }
                }
            }
        }
    __syncthreads();
}

__device__ __forceinline__ uint32_t smem_u32(const void* p) {
    uint32_t a;
    asm("{ .reg .u64 t; cvta.to.shared.u64 t, %1; cvt.u32.u64 %0, t; }" : "=r"(a) : "l"(p));
    return a;
}
__device__ __forceinline__ void st_cluster_f2(uint32_t addr, int rank, float2 v) {
    uint32_t r; unsigned long long u;
    asm volatile("mapa.shared::cluster.u32 %0, %1, %2;" : "=r"(r) : "r"(addr), "r"(rank));
    asm volatile("mov.b64 %0, {%1,%2};" : "=l"(u) : "f"(v.x), "f"(v.y));
    asm volatile("st.shared::cluster.b64 [%0], %1;" :: "r"(r), "l"(u) : "memory");
}
#define CLUSTER_SYNC() do { \
    asm volatile("barrier.cluster.arrive.aligned;" ::: "memory"); \
    asm volatile("barrier.cluster.wait.aligned;" ::: "memory"); } while (0)

// ---------------- stage 1: softmax + one-hot + pool ----------------
__global__ void pool_kernel(const float* __restrict__ x, const int* __restrict__ y) {
    int idx = blockIdx.x * blockDim.x + threadIdx.x;
    if (idx >= NIMG * NPX) return;
    int m = idx >> 10, cell = idx & 1023;
    int gi = cell >> 5, gj = cell & 31;
    float acc = 0.f;
    if (m < 12) {
        int b = m / 3, c = m % 3 + 1;
        const float* xb = x + (size_t)b * 4 * 65536;
        for (int pi = 0; pi < 8; ++pi) {
            int off0 = (gi * 8 + pi) * 256 + gj * 8;
            #pragma unroll
            for (int pj = 0; pj < 8; ++pj) {
                int off = off0 + pj;
                float x0 = xb[off], x1 = xb[65536 + off],
                      x2 = xb[131072 + off], x3 = xb[196608 + off];
                float mx = fmaxf(fmaxf(x0, x1), fmaxf(x2, x3));
                float e0 = __expf(x0 - mx), e1 = __expf(x1 - mx),
                      e2 = __expf(x2 - mx), e3 = __expf(x3 - mx);
                float ec = (c == 1) ? e1 : ((c == 2) ? e2 : e3);
                acc += ec / (e0 + e1 + e2 + e3);
            }
        }
    } else {
        int mm = m - 12, b = mm / 3, c = mm % 3 + 1;
        const int* yb = y + (size_t)b * 65536;
        int cnt = 0;
        for (int pi = 0; pi < 8; ++pi) {
            int off0 = (gi * 8 + pi) * 256 + gj * 8;
            #pragma unroll
            for (int pj = 0; pj < 8; ++pj) cnt += (yb[off0 + pj] == c);
        }
        acc = (float)cnt;
    }
    g_v[m][cell] = acc * 0.015625f;
}

// ---------------- stage 2: persistence diagrams ----------------
__global__ void diagram_kernel() {
    int m = blockIdx.x >> 1;
    int r = blockIdx.x & 1;
    __shared__ float v[NPX];
    __shared__ unsigned long long keys[2048];
    __shared__ float bArr[2048], dArr[2048];
    __shared__ int parent[NPX];
    __shared__ float birth[NPX];
    __shared__ float r8[8];
    int tid = threadIdx.x;

    for (int i = tid; i < NPX; i += 256) {
        float val = g_v[m][i];
        if (r) val = -val;
        v[i] = val; birth[i] = val; parent[i] = i;
    }
    __syncthreads();

    for (int e = tid; e < 2048; e += 256) {
        unsigned long long key = ~0ULL;
        if (e < NE) {
            int u, w2; edge_uv(e, u, w2);
            float w = fmaxf(v[u], v[w2]);
            key = ((unsigned long long)ordf(w) << 32) | (unsigned)e;
        }
        keys[e] = key;
    }
    float mn = v[tid], mx = v[tid];
    for (int i = tid + 256; i < NPX; i += 256) { mn = fminf(mn, v[i]); mx = fmaxf(mx, v[i]); }

    bitonic2048(keys);
    float vmax = blkMax(mx, r8);
    float vmin = -blkMax(-mn, r8);

    // warp-assisted exact Kruskal: 32 lanes pre-find roots, lane 0 commits in order
    if (tid < 32) {
        const unsigned FULL = 0xffffffffu;
        for (int base = 0; base < NE; base += 32) {   // NE = 62*32, no remainder
            int s = base + tid;
            int e = (int)(unsigned)keys[s];
            int u, vv; edge_uv(e, u, vv);
            float w = fmaxf(v[u], v[vv]);
            int ru = u;
            for (;;) { int p = parent[ru]; if (p == ru) break;
                       int g2 = parent[p]; parent[ru] = g2; ru = g2; }
            int rv = vv;
            for (;;) { int p = parent[rv]; if (p == rv) break;
                       int g2 = parent[p]; parent[rv] = g2; rv = g2; }
            __syncwarp();
            for (int l = 0; l < 32; ++l) {
                int ra = __shfl_sync(FULL, ru, l);
                int rb = __shfl_sync(FULL, rv, l);
                float wl = __shfl_sync(FULL, w, l);
                if (tid == 0) {
                    for (;;) { int p = parent[ra]; if (p == ra) break; ra = p; }
                    for (;;) { int p = parent[rb]; if (p == rb) break; rb = p; }
                    float b, d;
                    if (ra == rb) { b = wl; d = wl; }
                    else {
                        float ba = birth[ra], bb2 = birth[rb];
                        b = fmaxf(ba, bb2); d = wl;
                        if (ba <= bb2) { parent[rb] = ra; birth[ra] = fminf(ba, bb2); }
                        else           { parent[ra] = rb; birth[rb] = fminf(ba, bb2); }
                    }
                    bArr[base + l] = b; dArr[base + l] = d;
                }
            }
            __syncwarp();
        }
        if (tid == 0 && r == 0) { bArr[NE] = vmin; dArr[NE] = vmax; }
    }
    __syncthreads();

    int limit = (r == 0) ? NE + 1 : NE;
    for (int e = tid; e < 2048; e += 256) {
        unsigned long long key = ~0ULL;
        if (e < limit) {
            float pval = dArr[e] - bArr[e];
            key = ((unsigned long long)(~ordf(pval)) << 32) | (unsigned)e;
        }
        keys[e] = key;
    }
    bitonic2048(keys);

    if (tid < KTOP) {
        int s = (int)(unsigned)keys[tid];
        if (r == 0) {
            g_bd[m][0][0][tid] = bArr[s];
            g_bd[m][0][1][tid] = dArr[s];
        } else {
            g_bd[m][1][0][tid] = -dArr[s];
            g_bd[m][1][1][tid] = -bArr[s];
        }
    }
}

// ---------------- stage 3: clustered Sinkhorn ----------------
// 4 CTAs per problem. Rank q owns j-chunk [64q,64q+64) in the f-pass and
// i-chunk in the g-pass. Per half-iter: local partial (max,sum) over chunk ->
// DSMEM all-to-all of 256 float2 partials -> cluster sync -> full combine.
// Cost matrix precomputed once in smem, pre-scaled by 1/eps.
#define OFF_CSF 0
#define OFF_CSG 16384
#define OFF_PBF 32768            // float2[4*256]  (2048 floats)
#define OFF_PBG 34816
#define OFF_F   36864
#define OFF_G   37120
#define OFF_DAS 37376
#define OFF_DBS 37632
#define OFF_A   37888            // float2[256]
#define OFF_B   38400
#define OFF_RED 38912
#define SINK_SMEM_FLOATS 38920

__global__ void __cluster_dims__(CLU, 1, 1) sinkhorn_kernel() {
    extern __shared__ float sm[];
    float* csf = sm + OFF_CSF;               // [64][256]
    float* csg = sm + OFF_CSG;               // [64][256]
    float2* pbf = (float2*)(sm + OFF_PBF);   // flat [4*256]
    float2* pbg = (float2*)(sm + OFF_PBG);
    float* F = sm + OFF_F;
    float* G = sm + OFF_G;
    float* das = sm + OFF_DAS;
    float* dbs = sm + OFF_DBS;
    float2* Ash = (float2*)(sm + OFF_A);
    float2* Bsh = (float2*)(sm + OFF_B);
    float* r8 = sm + OFF_RED;

    int t = threadIdx.x;
    int p = blockIdx.x >> 2;
    int q = blockIdx.x & 3;
    int q64 = q * 64;
    int dim = (p < 12) ? 0 : 1;
    int img = (p < 12) ? p : p - 12;

    float ab = g_bd[img][dim][0][t],      ad = g_bd[img][dim][1][t];
    float bb = g_bd[12 + img][dim][0][t], bd = g_bd[12 + img][dim][1][t];
    float2 a = make_float2(ab, ad), b = make_float2(bb, bd);
    Ash[t] = a; Bsh[t] = b;
    float da = 0.5f * (ad - ab), db = 0.5f * (bd - bb);
    F[t] = 0.f; G[t] = 0.f;
    __syncthreads();

    // eps from full cost-matrix max (redundant per CTA, identical bitwise)
    float mC = fmaxf(da, db);
    #pragma unroll 4
    for (int i = 0; i < KTOP; ++i) {
        float2 aq = Ash[i];
        mC = fmaxf(mC, fmaxf(fabsf(aq.x - b.x), fabsf(aq.y - b.y)));
    }
    float eps = 0.02f * fmaxf(blkMax(mC, r8), 1e-6f);
    float ie = 1.f / eps;
    das[t] = da * ie; dbs[t] = db * ie;

    // scaled cost slices (thread t -> column t: conflict-free)
    #pragma unroll 4
    for (int jj = 0; jj < 64; ++jj) {                   // Cs_f[jj][i=t] = C(t, q64+jj)/eps
        float2 bq = Bsh[q64 + jj];
        csf[jj * 256 + t] = fmaxf(fabsf(a.x - bq.x), fabsf(a.y - bq.y)) * ie;
    }
    #pragma unroll 4
    for (int ii = 0; ii < 64; ++ii) {                   // Cs_g[ii][j=t] = C(q64+ii, t)/eps
        float2 aq = Ash[q64 + ii];
        csg[ii * 256 + t] = fmaxf(fabsf(aq.x - b.x), fabsf(aq.y - b.y)) * ie;
    }
    __syncthreads();
    CLUSTER_SYNC();

    uint32_t pbf_addr = smem_u32(&pbf[q * 256 + t]);
    uint32_t pbg_addr = smem_u32(&pbg[q * 256 + t]);
    float F2 = 0.f, G2 = 0.f;
    float mydas = das[t], mydbs = dbs[t];

    for (int it = 0; it < SINK_ITERS; ++it) {
        // ---- f partial over own j-chunk (thread t = row) ----
        float m = -3.4e38f;
        #pragma unroll 8
        for (int jj = 0; jj < 64; ++jj)
            m = fmaxf(m, G[q64 + jj] - csf[jj * 256 + t]);
        float s = 0.f;
        #pragma unroll 8
        for (int jj = 0; jj < 64; ++jj)
            s += __expf(G[q64 + jj] - csf[jj * 256 + t] - m);
        // F2 (full, redundant per CTA)
        float et = G[t] - mydbs;
        float M2 = blkMax(fmaxf(et, G2), r8);
        float S2 = blkSum(__expf(et - M2), r8) + 256.f * __expf(G2 - M2);
        float newF2 = -(M2 + __logf(S2));
        float2 part = make_float2(m, s);
        #pragma unroll
        for (int rr = 0; rr < CLU; ++rr) st_cluster_f2(pbf_addr, rr, part);
        CLUSTER_SYNC();
        {
            float2 p0 = pbf[t], p1 = pbf[256 + t], p2 = pbf[512 + t], p3 = pbf[768 + t];
            float tv = G2 - mydas;
            float mm = fmaxf(fmaxf(fmaxf(p0.x, p1.x), fmaxf(p2.x, p3.x)), tv);
            float ss = p0.y * __expf(p0.x - mm) + p1.y * __expf(p1.x - mm)
                     + p2.y * __expf(p2.x - mm) + p3.y * __expf(p3.x - mm)
                     + 256.f * __expf(tv - mm);
            F[t] = -(mm + __logf(ss));
            F2 = newF2;
        }
        __syncthreads();

        // ---- g partial over own i-chunk (thread t = col) ----
        m = -3.4e38f;
        #pragma unroll 8
        for (int ii = 0; ii < 64; ++ii)
            m = fmaxf(m, F[q64 + ii] - csg[ii * 256 + t]);
        s = 0.f;
        #pragma unroll 8
        for (int ii = 0; ii < 64; ++ii)
            s += __expf(F[q64 + ii] - csg[ii * 256 + t] - m);
        float eg = F[t] - mydas;
        float M3 = blkMax(fmaxf(eg, F2), r8);
        float S3 = blkSum(__expf(eg - M3), r8) + 256.f * __expf(F2 - M3);
        float newG2 = -(M3 + __logf(S3));
        part = make_float2(m, s);
        #pragma unroll
        for (int rr = 0; rr < CLU; ++rr) st_cluster_f2(pbg_addr, rr, part);
        CLUSTER_SYNC();
        {
            float2 p0 = pbg[t], p1 = pbg[256 + t], p2 = pbg[512 + t], p3 = pbg[768 + t];
            float tv = F2 - mydbs;
            float mm = fmaxf(fmaxf(fmaxf(p0.x, p1.x), fmaxf(p2.x, p3.x)), tv);
            float ss = p0.y * __expf(p0.x - mm) + p1.y * __expf(p1.x - mm)
                     + p2.y * __expf(p2.x - mm) + p3.y * __expf(p3.x - mm)
                     + 256.f * __expf(tv - mm);
            G[t] = -(mm + __logf(ss));
            G2 = newG2;
        }
        __syncthreads();
    }

    // ---- final cost partial: i-chunk rows of Mpp + chunked rank-1 terms ----
    float acc = 0.f;
    float myG = G[t];
    #pragma unroll 4
    for (int ii = 0; ii < 64; ++ii) {
        float cs = csg[ii * 256 + t];
        acc += __expf(F[q64 + ii] + myG - cs) * cs;
    }
    if (t < 64) {
        int i = q64 + t;
        acc += 256.f * __expf(F[i] + G2 - das[i]) * das[i];
        acc += 256.f * __expf(F2 + G[i] - dbs[i]) * dbs[i];
    }
    float tot = blkSum(acc, r8);
    if (t == 0) g_wpart[p * CLU + q] = tot * eps;
}

// ---------------- stage 4: deterministic reduction ----------------
__global__ void final_kernel(float* out) {
    float s = 0.f;
    for (int p = 0; p < NIMG; ++p) {
        float w = 0.f;
        for (int q = 0; q < CLU; ++q) w += g_wpart[p * CLU + q];
        s += w;
    }
    out[0] = s * 0.25f;
}

extern "C" void kernel_launch(void* const* d_in, const int* in_sizes, int n_in,
                              void* d_out, int out_size) {
    (void)in_sizes; (void)n_in; (void)out_size;
    const float* x = (const float*)d_in[0];
    const int* y = (const int*)d_in[1];
    static bool attr_set = false;
    if (!attr_set) {
        cudaFuncSetAttribute(sinkhorn_kernel,
                             cudaFuncAttributeMaxDynamicSharedMemorySize,
                             SINK_SMEM_FLOATS * 4);
        attr_set = true;
    }
    pool_kernel<<<(NIMG * NPX + 255) / 256, 256>>>(x, y);
    diagram_kernel<<<48, 256>>>();
    sinkhorn_kernel<<<NIMG * CLU, 256, SINK_SMEM_FLOATS * 4>>>();
    final_kernel<<<1, 1>>>((float*)d_out);
}

// round 4
// speedup vs baseline: 2.7409x; 1.0018x over previous
#include <cuda_runtime.h>
#include <cuda_bf16.h>
#include <cstdint>

#define GRIDSZ 32
#define NPX 1024
#define NE 1984
#define KTOP 256
#define NIMG 24
#define SINK_ITERS 150
#define CLU 4            // cluster size for sinkhorn

// ---------------- global scratch ----------------
__device__ float g_v[NIMG][NPX];
__device__ float g_bd[NIMG][2][2][KTOP];
__device__ float g_wpart[NIMG * CLU];

// ---------------- helpers ----------------
__device__ __forceinline__ unsigned ordf(float f) {
    unsigned u = __float_as_uint(f);
    return (u & 0x80000000u) ? ~u : (u | 0x80000000u);
}

__device__ __forceinline__ float blkMax(float v, float* r8) {
    #pragma unroll
    for (int o = 16; o; o >>= 1) v = fmaxf(v, __shfl_xor_sync(0xffffffffu, v, o));
    if ((threadIdx.x & 31) == 0) r8[threadIdx.x >> 5] = v;
    __syncthreads();
    float m = r8[0];
    #pragma unroll
    for (int k = 1; k < 8; ++k) m = fmaxf(m, r8[k]);
    __syncthreads();
    return m;
}
__device__ __forceinline__ float blkSum(float v, float* r8) {
    #pragma unroll
    for (int o = 16; o; o >>= 1) v += __shfl_xor_sync(0xffffffffu, v, o);
    if ((threadIdx.x & 31) == 0) r8[threadIdx.x >> 5] = v;
    __syncthreads();
    float s = r8[0];
    #pragma unroll
    for (int k = 1; k < 8; ++k) s += r8[k];
    __syncthreads();
    return s;
}

__device__ __forceinline__ void edge_uv(int e, int& u, int& v) {
    if (e < 992) { int rr = e / 31, cc = e - rr * 31; u = rr * 32 + cc; v = u + 1; }
    else { u = e - 992; v = u + 32; }
}

__device__ void bitonic2048(unsigned long long* keys) {
    int tid = threadIdx.x;
    for (unsigned k = 2; k <= 2048; k <<= 1)
        for (unsigned j = k >> 1; j > 0; j >>= 1) {
            __syncthreads();
            for (unsigned i = tid; i < 2048; i += 256) {
                unsigned l = i ^ j;
                if (l > i) {
                    unsigned long long a = keys[i], b = keys[l];
                    bool up = ((i & k) == 0);
                    if ((a > b) == up) { keys[i] = b; keys[l] = a; }
                }
            }
        }
    __syncthreads();
}

__device__ __forceinline__ uint32_t smem_u32(const void* p) {
    uint32_t a;
    asm("{ .reg .u64 t; cvta.to.shared.u64 t, %1; cvt.u32.u64 %0, t; }" : "=r"(a) : "l"(p));
    return a;
}
__device__ __forceinline__ void st_cluster_f2(uint32_t addr, int rank, float2 v) {
    uint32_t r; unsigned long long u;
    asm volatile("mapa.shared::cluster.u32 %0, %1, %2;" : "=r"(r) : "r"(addr), "r"(rank));
    asm volatile("mov.b64 %0, {%1,%2};" : "=l"(u) : "f"(v.x), "f"(v.y));
    asm volatile("st.shared::cluster.b64 [%0], %1;" :: "r"(r), "l"(u) : "memory");
}
#define CLUSTER_SYNC() do { \
    asm volatile("barrier.cluster.arrive.aligned;" ::: "memory"); \
    asm volatile("barrier.cluster.wait.aligned;" ::: "memory"); } while (0)

// ---------------- stage 1: softmax + one-hot + pool ----------------
__global__ void pool_kernel(const float* __restrict__ x, const int* __restrict__ y) {
    int idx = blockIdx.x * blockDim.x + threadIdx.x;
    if (idx >= NIMG * NPX) return;
    int m = idx >> 10, cell = idx & 1023;
    int gi = cell >> 5, gj = cell & 31;
    float acc = 0.f;
    if (m < 12) {
        int b = m / 3, c = m % 3 + 1;
        const float* xb = x + (size_t)b * 4 * 65536;
        for (int pi = 0; pi < 8; ++pi) {
            int off0 = (gi * 8 + pi) * 256 + gj * 8;
            #pragma unroll
            for (int pj = 0; pj < 8; ++pj) {
                int off = off0 + pj;
                float x0 = xb[off], x1 = xb[65536 + off],
                      x2 = xb[131072 + off], x3 = xb[196608 + off];
                float mx = fmaxf(fmaxf(x0, x1), fmaxf(x2, x3));
                float e0 = __expf(x0 - mx), e1 = __expf(x1 - mx),
                      e2 = __expf(x2 - mx), e3 = __expf(x3 - mx);
                float ec = (c == 1) ? e1 : ((c == 2) ? e2 : e3);
                acc += ec / (e0 + e1 + e2 + e3);
            }
        }
    } else {
        int mm = m - 12, b = mm / 3, c = mm % 3 + 1;
        const int* yb = y + (size_t)b * 65536;
        int cnt = 0;
        for (int pi = 0; pi < 8; ++pi) {
            int off0 = (gi * 8 + pi) * 256 + gj * 8;
            #pragma unroll
            for (int pj = 0; pj < 8; ++pj) cnt += (yb[off0 + pj] == c);
        }
        acc = (float)cnt;
    }
    g_v[m][cell] = acc * 0.015625f;
}

// ---------------- stage 2: persistence diagrams ----------------
__global__ void diagram_kernel() {
    int m = blockIdx.x >> 1;
    int r = blockIdx.x & 1;
    __shared__ float v[NPX];
    __shared__ unsigned long long keys[2048];
    __shared__ float bArr[2048], dArr[2048];
    __shared__ int parent[NPX];
    __shared__ float birth[NPX];
    __shared__ float r8[8];
    int tid = threadIdx.x;

    for (int i = tid; i < NPX; i += 256) {
        float val = g_v[m][i];
        if (r) val = -val;
        v[i] = val; birth[i] = val; parent[i] = i;
    }
    __syncthreads();

    for (int e = tid; e < 2048; e += 256) {
        unsigned long long key = ~0ULL;
        if (e < NE) {
            int u, w2; edge_uv(e, u, w2);
            float w = fmaxf(v[u], v[w2]);
            key = ((unsigned long long)ordf(w) << 32) | (unsigned)e;
        }
        keys[e] = key;
    }
    float mn = v[tid], mx = v[tid];
    for (int i = tid + 256; i < NPX; i += 256) { mn = fminf(mn, v[i]); mx = fmaxf(mx, v[i]); }

    bitonic2048(keys);
    float vmax = blkMax(mx, r8);
    float vmin = -blkMax(-mn, r8);

    // warp-assisted exact Kruskal: 32 lanes pre-find roots, lane 0 commits in order
    if (tid < 32) {
        const unsigned FULL = 0xffffffffu;
        for (int base = 0; base < NE; base += 32) {   // NE = 62*32, no remainder
            int s = base + tid;
            int e = (int)(unsigned)keys[s];
            int u, vv; edge_uv(e, u, vv);
            float w = fmaxf(v[u], v[vv]);
            int ru = u;
            for (;;) { int p = parent[ru]; if (p == ru) break;
                       int g2 = parent[p]; parent[ru] = g2; ru = g2; }
            int rv = vv;
            for (;;) { int p = parent[rv]; if (p == rv) break;
                       int g2 = parent[p]; parent[rv] = g2; rv = g2; }
            __syncwarp();
            for (int l = 0; l < 32; ++l) {
                int ra = __shfl_sync(FULL, ru, l);
                int rb = __shfl_sync(FULL, rv, l);
                float wl = __shfl_sync(FULL, w, l);
                if (tid == 0) {
                    for (;;) { int p = parent[ra]; if (p == ra) break; ra = p; }
                    for (;;) { int p = parent[rb]; if (p == rb) break; rb = p; }
                    float b, d;
                    if (ra == rb) { b = wl; d = wl; }
                    else {
                        float ba = birth[ra], bb2 = birth[rb];
                        b = fmaxf(ba, bb2); d = wl;
                        if (ba <= bb2) { parent[rb] = ra; birth[ra] = fminf(ba, bb2); }
                        else           { parent[ra] = rb; birth[rb] = fminf(ba, bb2); }
                    }
                    bArr[base + l] = b; dArr[base + l] = d;
                }
            }
            __syncwarp();
        }
        if (tid == 0 && r == 0) { bArr[NE] = vmin; dArr[NE] = vmax; }
    }
    __syncthreads();

    int limit = (r == 0) ? NE + 1 : NE;
    for (int e = tid; e < 2048; e += 256) {
        unsigned long long key = ~0ULL;
        if (e < limit) {
            float pval = dArr[e] - bArr[e];
            key = ((unsigned long long)(~ordf(pval)) << 32) | (unsigned)e;
        }
        keys[e] = key;
    }
    bitonic2048(keys);

    if (tid < KTOP) {
        int s = (int)(unsigned)keys[tid];
        if (r == 0) {
            g_bd[m][0][0][tid] = bArr[s];
            g_bd[m][0][1][tid] = dArr[s];
        } else {
            g_bd[m][1][0][tid] = -dArr[s];
            g_bd[m][1][1][tid] = -bArr[s];
        }
    }
}

// ---------------- stage 3: clustered Sinkhorn ----------------
// 4 CTAs per problem. Rank q owns j-chunk [64q,64q+64) in the f-pass and
// i-chunk in the g-pass. Per half-iter: local partial (max,sum) over chunk ->
// DSMEM all-to-all of 256 float2 partials -> cluster sync -> full combine.
// Cost matrix precomputed once in smem, pre-scaled by 1/eps.
#define OFF_CSF 0
#define OFF_CSG 16384
#define OFF_PBF 32768            // float2[4*256]  (2048 floats)
#define OFF_PBG 34816
#define OFF_F   36864
#define OFF_G   37120
#define OFF_DAS 37376
#define OFF_DBS 37632
#define OFF_A   37888            // float2[256]
#define OFF_B   38400
#define OFF_RED 38912
#define SINK_SMEM_FLOATS 38920

__global__ void __cluster_dims__(CLU, 1, 1) sinkhorn_kernel() {
    extern __shared__ float sm[];
    float* csf = sm + OFF_CSF;               // [64][256]
    float* csg = sm + OFF_CSG;               // [64][256]
    float2* pbf = (float2*)(sm + OFF_PBF);   // flat [4*256]
    float2* pbg = (float2*)(sm + OFF_PBG);
    float* F = sm + OFF_F;
    float* G = sm + OFF_G;
    float* das = sm + OFF_DAS;
    float* dbs = sm + OFF_DBS;
    float2* Ash = (float2*)(sm + OFF_A);
    float2* Bsh = (float2*)(sm + OFF_B);
    float* r8 = sm + OFF_RED;

    int t = threadIdx.x;
    int p = blockIdx.x >> 2;
    int q = blockIdx.x & 3;
    int q64 = q * 64;
    int dim = (p < 12) ? 0 : 1;
    int img = (p < 12) ? p : p - 12;

    float ab = g_bd[img][dim][0][t],      ad = g_bd[img][dim][1][t];
    float bb = g_bd[12 + img][dim][0][t], bd = g_bd[12 + img][dim][1][t];
    float2 a = make_float2(ab, ad), b = make_float2(bb, bd);
    Ash[t] = a; Bsh[t] = b;
    float da = 0.5f * (ad - ab), db = 0.5f * (bd - bb);
    F[t] = 0.f; G[t] = 0.f;
    __syncthreads();

    // eps from full cost-matrix max (redundant per CTA, identical bitwise)
    float mC = fmaxf(da, db);
    #pragma unroll 4
    for (int i = 0; i < KTOP; ++i) {
        float2 aq = Ash[i];
        mC = fmaxf(mC, fmaxf(fabsf(aq.x - b.x), fabsf(aq.y - b.y)));
    }
    float eps = 0.02f * fmaxf(blkMax(mC, r8), 1e-6f);
    float ie = 1.f / eps;
    das[t] = da * ie; dbs[t] = db * ie;

    // scaled cost slices (thread t -> column t: conflict-free)
    #pragma unroll 4
    for (int jj = 0; jj < 64; ++jj) {                   // Cs_f[jj][i=t] = C(t, q64+jj)/eps
        float2 bq = Bsh[q64 + jj];
        csf[jj * 256 + t] = fmaxf(fabsf(a.x - bq.x), fabsf(a.y - bq.y)) * ie;
    }
    #pragma unroll 4
    for (int ii = 0; ii < 64; ++ii) {                   // Cs_g[ii][j=t] = C(q64+ii, t)/eps
        float2 aq = Ash[q64 + ii];
        csg[ii * 256 + t] = fmaxf(fabsf(aq.x - b.x), fabsf(aq.y - b.y)) * ie;
    }
    __syncthreads();
    CLUSTER_SYNC();

    uint32_t pbf_addr = smem_u32(&pbf[q * 256 + t]);
    uint32_t pbg_addr = smem_u32(&pbg[q * 256 + t]);
    float F2 = 0.f, G2 = 0.f;
    float mydas = das[t], mydbs = dbs[t];

    for (int it = 0; it < SINK_ITERS; ++it) {
        // ---- f partial over own j-chunk (thread t = row) ----
        float m = -3.4e38f;
        #pragma unroll 8
        for (int jj = 0; jj < 64; ++jj)
            m = fmaxf(m, G[q64 + jj] - csf[jj * 256 + t]);
        float s = 0.f;
        #pragma unroll 8
        for (int jj = 0; jj < 64; ++jj)
            s += __expf(G[q64 + jj] - csf[jj * 256 + t] - m);
        // F2 (full, redundant per CTA)
        float et = G[t] - mydbs;
        float M2 = blkMax(fmaxf(et, G2), r8);
        float S2 = blkSum(__expf(et - M2), r8) + 256.f * __expf(G2 - M2);
        float newF2 = -(M2 + __logf(S2));
        float2 part = make_float2(m, s);
        #pragma unroll
        for (int rr = 0; rr < CLU; ++rr) st_cluster_f2(pbf_addr, rr, part);
        CLUSTER_SYNC();
        {
            float2 p0 = pbf[t], p1 = pbf[256 + t], p2 = pbf[512 + t], p3 = pbf[768 + t];
            float tv = G2 - mydas;
            float mm = fmaxf(fmaxf(fmaxf(p0.x, p1.x), fmaxf(p2.x, p3.x)), tv);
            float ss = p0.y * __expf(p0.x - mm) + p1.y * __expf(p1.x - mm)
                     + p2.y * __expf(p2.x - mm) + p3.y * __expf(p3.x - mm)
                     + 256.f * __expf(tv - mm);
            F[t] = -(mm + __logf(ss));
            F2 = newF2;
        }
        __syncthreads();

        // ---- g partial over own i-chunk (thread t = col) ----
        m = -3.4e38f;
        #pragma unroll 8
        for (int ii = 0; ii < 64; ++ii)
            m = fmaxf(m, F[q64 + ii] - csg[ii * 256 + t]);
        s = 0.f;
        #pragma unroll 8
        for (int ii = 0; ii < 64; ++ii)
            s += __expf(F[q64 + ii] - csg[ii * 256 + t] - m);
        float eg = F[t] - mydas;
        float M3 = blkMax(fmaxf(eg, F2), r8);
        float S3 = blkSum(__expf(eg - M3), r8) + 256.f * __expf(F2 - M3);
        float newG2 = -(M3 + __logf(S3));
        part = make_float2(m, s);
        #pragma unroll
        for (int rr = 0; rr < CLU; ++rr) st_cluster_f2(pbg_addr, rr, part);
        CLUSTER_SYNC();
        {
            float2 p0 = pbg[t], p1 = pbg[256 + t], p2 = pbg[512 + t], p3 = pbg[768 + t];
            float tv = F2 - mydbs;
            float mm = fmaxf(fmaxf(fmaxf(p0.x, p1.x), fmaxf(p2.x, p3.x)), tv);
            float ss = p0.y * __expf(p0.x - mm) + p1.y * __expf(p1.x - mm)
                     + p2.y * __expf(p2.x - mm) + p3.y * __expf(p3.x - mm)
                     + 256.f * __expf(tv - mm);
            G[t] = -(mm + __logf(ss));
            G2 = newG2;
        }
        __syncthreads();
    }

    // ---- final cost partial: i-chunk rows of Mpp + chunked rank-1 terms ----
    float acc = 0.f;
    float myG = G[t];
    #pragma unroll 4
    for (int ii = 0; ii < 64; ++ii) {
        float cs = csg[ii * 256 + t];
        acc += __expf(F[q64 + ii] + myG - cs) * cs;
    }
    if (t < 64) {
        int i = q64 + t;
        acc += 256.f * __expf(F[i] + G2 - das[i]) * das[i];
        acc += 256.f * __expf(F2 + G[i] - dbs[i]) * dbs[i];
    }
    float tot = blkSum(acc, r8);
    if (t == 0) g_wpart[p * CLU + q] = tot * eps;
}

// ---------------- stage 4: deterministic reduction ----------------
__global__ void final_kernel(float* out) {
    float s = 0.f;
    for (int p = 0; p < NIMG; ++p) {
        float w = 0.f;
        for (int q = 0; q < CLU; ++q) w += g_wpart[p * CLU + q];
        s += w;
    }
    out[0] = s * 0.25f;
}

extern "C" void kernel_launch(void* const* d_in, const int* in_sizes, int n_in,
                              void* d_out, int out_size) {
    (void)in_sizes; (void)n_in; (void)out_size;
    const float* x = (const float*)d_in[0];
    const int* y = (const int*)d_in[1];
    static bool attr_set = false;
    if (!attr_set) {
        cudaFuncSetAttribute(sinkhorn_kernel,
                             cudaFuncAttributeMaxDynamicSharedMemorySize,
                             SINK_SMEM_FLOATS * 4);
        attr_set = true;
    }
    pool_kernel<<<(NIMG * NPX + 255) / 256, 256>>>(x, y);
    diagram_kernel<<<48, 256>>>();
    sinkhorn_kernel<<<NIMG * CLU, 256, SINK_SMEM_FLOATS * 4>>>();
    final_kernel<<<1, 1>>>((float*)d_out);
}

// round 5
// speedup vs baseline: 4.6456x; 1.6949x over previous
#include <cuda_runtime.h>
#include <cuda_bf16.h>
#include <cstdint>

#define NPX 1024
#define NE 1984
#define KTOP 256
#define NIMG 24
#define SINK_ITERS 150
#define CLU 4

__device__ float g_v[NIMG][NPX];
__device__ float g_bd[NIMG][2][2][KTOP];
__device__ float g_wpart[NIMG * CLU];

__device__ __forceinline__ unsigned ordf(float f) {
    unsigned u = __float_as_uint(f);
    return (u & 0x80000000u) ? ~u : (u | 0x80000000u);
}

__device__ __forceinline__ float blkMax(float v, float* r8) {
    #pragma unroll
    for (int o = 16; o; o >>= 1) v = fmaxf(v, __shfl_xor_sync(0xffffffffu, v, o));
    if ((threadIdx.x & 31) == 0) r8[threadIdx.x >> 5] = v;
    __syncthreads();
    float m = r8[0];
    #pragma unroll
    for (int k = 1; k < 8; ++k) m = fmaxf(m, r8[k]);
    __syncthreads();
    return m;
}
__device__ __forceinline__ float blkSum(float v, float* r8) {
    #pragma unroll
    for (int o = 16; o; o >>= 1) v += __shfl_xor_sync(0xffffffffu, v, o);
    if ((threadIdx.x & 31) == 0) r8[threadIdx.x >> 5] = v;
    __syncthreads();
    float s = r8[0];
    #pragma unroll
    for (int k = 1; k < 8; ++k) s += r8[k];
    __syncthreads();
    return s;
}

__device__ __forceinline__ void edge_uv(int e, int& u, int& v) {
    if (e < 992) { int rr = e / 31, cc = e - rr * 31; u = rr * 32 + cc; v = u + 1; }
    else { u = e - 992; v = u + 32; }
}

__device__ void bitonic2048(unsigned long long* keys) {
    int tid = threadIdx.x;
    for (unsigned k = 2; k <= 2048; k <<= 1)
        for (unsigned j = k >> 1; j > 0; j >>= 1) {
            __syncthreads();
            for (unsigned i = tid; i < 2048; i += 256) {
                unsigned l = i ^ j;
                if (l > i) {
                    unsigned long long a = keys[i], b = keys[l];
                    bool up = ((i & k) == 0);
                    if ((a > b) == up) { keys[i] = b; keys[l] = a; }
                }
            }
        }
    __syncthreads();
}

__device__ __forceinline__ uint32_t smem_u32(const void* p) {
    uint32_t a;
    asm("{ .reg .u64 t; cvta.to.shared.u64 t, %1; cvt.u32.u64 %0, t; }" : "=r"(a) : "l"(p));
    return a;
}
__device__ __forceinline__ void st_cluster_f32(uint32_t addr, int rank, float v) {
    uint32_t r;
    asm volatile("mapa.shared::cluster.u32 %0, %1, %2;" : "=r"(r) : "r"(addr), "r"(rank));
    asm volatile("st.shared::cluster.b32 [%0], %1;" :: "r"(r), "f"(v) : "memory");
}
#define CLUSTER_SYNC() do { \
    asm volatile("barrier.cluster.arrive.aligned;" ::: "memory"); \
    asm volatile("barrier.cluster.wait.aligned;" ::: "memory"); } while (0)

// ---------------- stage 1: softmax + one-hot + pool ----------------
__global__ void pool_kernel(const float* __restrict__ x, const int* __restrict__ y) {
    int idx = blockIdx.x * blockDim.x + threadIdx.x;
    if (idx >= NIMG * NPX) return;
    int m = idx >> 10, cell = idx & 1023;
    int gi = cell >> 5, gj = cell & 31;
    float acc = 0.f;
    if (m < 12) {
        int b = m / 3, c = m % 3 + 1;
        const float* xb = x + (size_t)b * 4 * 65536;
        for (int pi = 0; pi < 8; ++pi) {
            int off0 = (gi * 8 + pi) * 256 + gj * 8;
            #pragma unroll
            for (int pj = 0; pj < 8; ++pj) {
                int off = off0 + pj;
                float x0 = xb[off], x1 = xb[65536 + off],
                      x2 = xb[131072 + off], x3 = xb[196608 + off];
                float mx = fmaxf(fmaxf(x0, x1), fmaxf(x2, x3));
                float e0 = __expf(x0 - mx), e1 = __expf(x1 - mx),
                      e2 = __expf(x2 - mx), e3 = __expf(x3 - mx);
                float ec = (c == 1) ? e1 : ((c == 2) ? e2 : e3);
                acc += ec / (e0 + e1 + e2 + e3);
            }
        }
    } else {
        int mm = m - 12, b = mm / 3, c = mm % 3 + 1;
        const int* yb = y + (size_t)b * 65536;
        int cnt = 0;
        for (int pi = 0; pi < 8; ++pi) {
            int off0 = (gi * 8 + pi) * 256 + gj * 8;
            #pragma unroll
            for (int pj = 0; pj < 8; ++pj) cnt += (yb[off0 + pj] == c);
        }
        acc = (float)cnt;
    }
    g_v[m][cell] = acc * 0.015625f;
}

// ---------------- stage 2: persistence diagrams ----------------
__global__ void diagram_kernel() {
    int m = blockIdx.x >> 1;
    int r = blockIdx.x & 1;
    __shared__ float v[NPX];
    __shared__ unsigned long long keys[2048];
    __shared__ float bArr[2048], dArr[2048];
    __shared__ int parent[NPX];
    __shared__ float birth[NPX];
    __shared__ float r8[8];
    __shared__ int sRu[32], sRv[32];
    __shared__ float sW[32];
    int tid = threadIdx.x;

    for (int i = tid; i < NPX; i += 256) {
        float val = g_v[m][i];
        if (r) val = -val;
        v[i] = val; birth[i] = val; parent[i] = i;
    }
    __syncthreads();

    for (int e = tid; e < 2048; e += 256) {
        unsigned long long key = ~0ULL;
        if (e < NE) {
            int u, w2; edge_uv(e, u, w2);
            float w = fmaxf(v[u], v[w2]);
            key = ((unsigned long long)ordf(w) << 32) | (unsigned)e;
        }
        keys[e] = key;
    }
    float mn = v[tid], mx = v[tid];
    for (int i = tid + 256; i < NPX; i += 256) { mn = fminf(mn, v[i]); mx = fmaxf(mx, v[i]); }

    bitonic2048(keys);
    float vmax = blkMax(mx, r8);
    float vmin = -blkMax(-mn, r8);

    // warp-assisted exact Kruskal: lanes pre-find roots into smem stage,
    // lane 0 re-validates and commits in exact sorted order.
    if (tid < 32) {
        for (int base = 0; base < NE; base += 32) {   // NE = 62*32
            int s = base + tid;
            int e = (int)(unsigned)keys[s];
            int u, vv; edge_uv(e, u, vv);
            float w = fmaxf(v[u], v[vv]);
            int ru = u;
            for (;;) { int p = parent[ru]; if (p == ru) break;
                       int g2 = parent[p]; parent[ru] = g2; ru = g2; }
            int rv = vv;
            for (;;) { int p = parent[rv]; if (p == rv) break;
                       int g2 = parent[p]; parent[rv] = g2; rv = g2; }
            sRu[tid] = ru; sRv[tid] = rv; sW[tid] = w;
            __syncwarp();
            if (tid == 0) {
                #pragma unroll 4
                for (int l = 0; l < 32; ++l) {
                    int ra = sRu[l], rb = sRv[l];
                    float wl = sW[l];
                    while (parent[ra] != ra) ra = parent[ra];
                    while (parent[rb] != rb) rb = parent[rb];
                    float b, d;
                    if (ra == rb) { b = wl; d = wl; }
                    else {
                        float ba = birth[ra], bb2 = birth[rb];
                        b = fmaxf(ba, bb2); d = wl;
                        if (ba <= bb2) { parent[rb] = ra; birth[ra] = fminf(ba, bb2); }
                        else           { parent[ra] = rb; birth[rb] = fminf(ba, bb2); }
                    }
                    bArr[base + l] = b; dArr[base + l] = d;
                }
            }
            __syncwarp();
        }
        if (tid == 0 && r == 0) { bArr[NE] = vmin; dArr[NE] = vmax; }
    }
    __syncthreads();

    int limit = (r == 0) ? NE + 1 : NE;
    for (int e = tid; e < 2048; e += 256) {
        unsigned long long key = ~0ULL;
        if (e < limit) {
            float pval = dArr[e] - bArr[e];
            key = ((unsigned long long)(~ordf(pval)) << 32) | (unsigned)e;
        }
        keys[e] = key;
    }
    bitonic2048(keys);

    if (tid < KTOP) {
        int s = (int)(unsigned)keys[tid];
        if (r == 0) {
            g_bd[m][0][0][tid] = bArr[s];
            g_bd[m][0][1][tid] = dArr[s];
        } else {
            g_bd[m][1][0][tid] = -dArr[s];
            g_bd[m][1][1][tid] = -bArr[s];
        }
    }
}

// ---------------- stage 3: factorized clustered Sinkhorn ----------------
// E = exp(-C/eps) precomputed; EG_j = exp(phiG_j - K_G). Row LSE becomes a dot
// product. One float exchanged per thread per half-iter + 1 cluster sync.
// warp0 computes the diagonal potential (F2/G2) locally (EG replicated).
#define OFF_EFM 0                 // Ef [64][256]
#define OFF_EGM 16384             // Eg [64][256]
#define OFF_PBF 32768             // float[4*256]
#define OFF_PBG 33792
#define OFF_F   34816
#define OFF_G   35072
#define OFF_EXG 35328             // EG vec
#define OFF_EXF 35584             // EF vec
#define OFF_EDA 35840
#define OFF_EDB 36096
#define OFF_DAS 36352
#define OFF_DBS 36608
#define OFF_A   36864             // float2[256]
#define OFF_B   37376
#define OFF_RED 37888
#define OFF_SC  37896             // [0]=F2 [1]=G2 [2]=EF2 [3]=EG2
#define SINK_SMEM_FLOATS 37904

__global__ void __cluster_dims__(CLU, 1, 1) sinkhorn_kernel() {
    extern __shared__ float sm[];
    float* Ef = sm + OFF_EFM;
    float* Eg = sm + OFF_EGM;
    float* pbf = sm + OFF_PBF;
    float* pbg = sm + OFF_PBG;
    float* F = sm + OFF_F;
    float* G = sm + OFF_G;
    float* EG = sm + OFF_EXG;
    float* EF = sm + OFF_EXF;
    float* EDA = sm + OFF_EDA;
    float* EDB = sm + OFF_EDB;
    float* das = sm + OFF_DAS;
    float* dbs = sm + OFF_DBS;
    float2* Ash = (float2*)(sm + OFF_A);
    float2* Bsh = (float2*)(sm + OFF_B);
    float* r8 = sm + OFF_RED;
    float* sc = sm + OFF_SC;

    int t = threadIdx.x;
    int p = blockIdx.x >> 2;
    int q = blockIdx.x & 3;
    int q64 = q * 64;
    int dim = (p < 12) ? 0 : 1;
    int img = (p < 12) ? p : p - 12;

    float ab = g_bd[img][dim][0][t],      ad = g_bd[img][dim][1][t];
    float bb = g_bd[12 + img][dim][0][t], bd = g_bd[12 + img][dim][1][t];
    float2 a = make_float2(ab, ad), b = make_float2(bb, bd);
    Ash[t] = a; Bsh[t] = b;
    float da = 0.5f * (ad - ab), db = 0.5f * (bd - bb);
    F[t] = 0.f; G[t] = 0.f; EG[t] = 1.f;
    if (t < 4) sc[t] = (t < 2) ? 0.f : 1.f;   // F2=G2=0, EF2=EG2=1
    __syncthreads();

    // eps (bitwise identical on every CTA)
    float mC = fmaxf(da, db);
    #pragma unroll 4
    for (int i = 0; i < KTOP; ++i) {
        float2 aq = Ash[i];
        mC = fmaxf(mC, fmaxf(fabsf(aq.x - b.x), fabsf(aq.y - b.y)));
    }
    float eps = 0.02f * fmaxf(blkMax(mC, r8), 1e-6f);
    float ie = 1.f / eps;
    das[t] = da * ie; dbs[t] = db * ie;
    EDA[t] = __expf(-da * ie); EDB[t] = __expf(-db * ie);

    #pragma unroll 4
    for (int jj = 0; jj < 64; ++jj) {                   // Ef[jj][i=t] = exp(-C(t,q64+jj)/eps)
        float2 bq = Bsh[q64 + jj];
        Ef[jj * 256 + t] = __expf(-fmaxf(fabsf(a.x - bq.x), fabsf(a.y - bq.y)) * ie);
    }
    #pragma unroll 4
    for (int ii = 0; ii < 64; ++ii) {                   // Eg[ii][j=t] = exp(-C(q64+ii,t)/eps)
        float2 aq = Ash[q64 + ii];
        Eg[ii * 256 + t] = __expf(-fmaxf(fabsf(aq.x - b.x), fabsf(aq.y - b.y)) * ie);
    }
    __syncthreads();
    CLUSTER_SYNC();

    uint32_t pbf_addr = smem_u32(&pbf[q * 256 + t]);
    uint32_t pbg_addr = smem_u32(&pbg[q * 256 + t]);
    float K_G = 0.f, K_F;
    float myEDA = EDA[t], myEDB = EDB[t];

    for (int it = 0; it < SINK_ITERS; ++it) {
        // ---- f half-iter ----
        float s = 0.f;
        #pragma unroll 8
        for (int jj = 0; jj < 64; ++jj)
            s = fmaf(EG[q64 + jj], Ef[jj * 256 + t], s);
        if (t < 32) {                                   // warp0: F2 (full, local)
            float s2 = 0.f;
            #pragma unroll
            for (int k = 0; k < 8; ++k) {
                int j = t + k * 32;
                s2 = fmaf(EG[j], EDB[j], s2);
            }
            #pragma unroll
            for (int o = 16; o; o >>= 1) s2 += __shfl_xor_sync(0xffffffffu, s2, o);
            if (t == 0) sc[0] = -(K_G + __logf(s2 + 256.f * sc[3]));
        }
        #pragma unroll
        for (int rr = 0; rr < CLU; ++rr) st_cluster_f32(pbf_addr, rr, s);
        CLUSTER_SYNC();
        float S = pbf[t] + pbf[256 + t] + pbf[512 + t] + pbf[768 + t]
                + 256.f * sc[3] * myEDA;
        float phiF = -(K_G + __logf(S));
        F[t] = phiF;
        K_F = blkMax(phiF, r8);
        EF[t] = __expf(phiF - K_F);
        if (t == 0) sc[2] = __expf(sc[0] - K_F);
        __syncthreads();

        // ---- g half-iter ----
        s = 0.f;
        #pragma unroll 8
        for (int ii = 0; ii < 64; ++ii)
            s = fmaf(EF[q64 + ii], Eg[ii * 256 + t], s);
        if (t < 32) {                                   // warp0: G2
            float s2 = 0.f;
            #pragma unroll
            for (int k = 0; k < 8; ++k) {
                int i = t + k * 32;
                s2 = fmaf(EF[i], EDA[i], s2);
            }
            #pragma unroll
            for (int o = 16; o; o >>= 1) s2 += __shfl_xor_sync(0xffffffffu, s2, o);
            if (t == 0) sc[1] = -(K_F + __logf(s2 + 256.f * sc[2]));
        }
        #pragma unroll
        for (int rr = 0; rr < CLU; ++rr) st_cluster_f32(pbg_addr, rr, s);
        CLUSTER_SYNC();
        S = pbg[t] + pbg[256 + t] + pbg[512 + t] + pbg[768 + t]
          + 256.f * sc[2] * myEDB;
        float phiG = -(K_F + __logf(S));
        G[t] = phiG;
        K_G = blkMax(phiG, r8);
        EG[t] = __expf(phiG - K_G);
        if (t == 0) sc[3] = __expf(sc[1] - K_G);
        __syncthreads();
    }

    // ---- final cost partial (i-chunk rows + chunked rank-1 terms) ----
    float acc = 0.f;
    float myG = G[t];
    #pragma unroll 4
    for (int ii = 0; ii < 64; ++ii) {
        float2 aq = Ash[q64 + ii];
        float cs = fmaxf(fabsf(aq.x - b.x), fabsf(aq.y - b.y)) * ie;
        acc += __expf(F[q64 + ii] + myG - cs) * cs;
    }
    if (t < 64) {
        int i = q64 + t;
        acc += 256.f * __expf(F[i] + sc[1] - das[i]) * das[i];
        acc += 256.f * __expf(sc[0] + G[i] - dbs[i]) * dbs[i];
    }
    float tot = blkSum(acc, r8);
    if (t == 0) g_wpart[p * CLU + q] = tot * eps;
}

// ---------------- stage 4: deterministic reduction ----------------
__global__ void final_kernel(float* out) {
    float s = 0.f;
    for (int p = 0; p < NIMG; ++p) {
        float w = 0.f;
        for (int q = 0; q < CLU; ++q) w += g_wpart[p * CLU + q];
        s += w;
    }
    out[0] = s * 0.25f;
}

extern "C" void kernel_launch(void* const* d_in, const int* in_sizes, int n_in,
                              void* d_out, int out_size) {
    (void)in_sizes; (void)n_in; (void)out_size;
    const float* x = (const float*)d_in[0];
    const int* y = (const int*)d_in[1];
    static bool attr_set = false;
    if (!attr_set) {
        cudaFuncSetAttribute(sinkhorn_kernel,
                             cudaFuncAttributeMaxDynamicSharedMemorySize,
                             SINK_SMEM_FLOATS * 4);
        attr_set = true;
    }
    pool_kernel<<<(NIMG * NPX + 255) / 256, 256>>>(x, y);
    diagram_kernel<<<48, 256>>>();
    sinkhorn_kernel<<<NIMG * CLU, 256, SINK_SMEM_FLOATS * 4>>>();
    final_kernel<<<1, 1>>>((float*)d_out);
}